// round 4
// baseline (speedup 1.0000x reference)
#include <cuda_runtime.h>
#include <math.h>

#define B      32
#define NITEMS 16384
#define D      128
#define IDIM   64

// ---------------- device scratch (no allocation allowed) ----------------
__device__ float g_scores[B * NITEMS];   // 2 MB, fits L2
__device__ float g_u[B * D];             // per-batch score vector (scale folded in)
__device__ float g_const[B];             // per-batch score constant (scale folded in)
__device__ float g_tau[B];
__device__ float g_asum[B];              // sum of relu(z - tau)
__device__ float g_sacc[B * D];          // sum_n relu(score-tau) * g[b,n]
__device__ unsigned int g_done;

// Branch-free erf-gelu: Abramowitz-Stegun 7.1.26, |abs err| <= 1.5e-7 on erf.
__device__ __forceinline__ float gelu_f(float x) {
    float ax = fabsf(x) * 0.7071067811865476f;          // |x|/sqrt(2)
    float t  = __fdividef(1.0f, fmaf(0.3275911f, ax, 1.0f));
    float p  = t * fmaf(t, fmaf(t, fmaf(t, fmaf(t, 1.061405429f, -1.453152027f),
                                        1.421413741f), -0.284496736f), 0.254829592f);
    float e  = __expf(-ax * ax);
    float erf_ax = fmaf(-p, e, 1.0f);                   // erf(|x|/sqrt(2))
    return 0.5f * x * (1.0f + copysignf(erf_ax, x));
}

// ---------------- prep: per-batch query path + folded vectors + init ----------------
// u[b]  = scale * wx2 @ (wkp @ q[b])
// c[b]  = scale * (bx2 . (wkp @ q[b]) + q[b] . bkp)
__global__ void prep_kernel(const float* __restrict__ x_query,
                            const float* __restrict__ wq1, const float* __restrict__ bq1,
                            const float* __restrict__ wq2, const float* __restrict__ bq2,
                            const float* __restrict__ wqp, const float* __restrict__ bqp,
                            const float* __restrict__ wkp, const float* __restrict__ bkp,
                            const float* __restrict__ wx2, const float* __restrict__ bx2) {
    int b = blockIdx.x;
    int j = threadIdx.x;
    __shared__ float h1[D], hq[D], qv[D], av[D], red[D];

    g_sacc[b * D + j] = 0.0f;            // fused init
    if (b == 0 && j == 0) g_done = 0u;

    float xq = x_query[b];
    h1[j] = gelu_f(fmaf(xq, wq1[j], bq1[j]));
    __syncthreads();

    float acc = bq2[j];
    #pragma unroll 8
    for (int i = 0; i < D; i++) acc = fmaf(h1[i], wq2[i * D + j], acc);
    hq[j] = acc;
    __syncthreads();

    acc = bqp[j];
    #pragma unroll 8
    for (int i = 0; i < D; i++) acc = fmaf(hq[i], wqp[i * D + j], acc);
    qv[j] = acc;                       // q[b][j]
    __syncthreads();

    acc = 0.0f;                        // a = wkp @ q : a_j = sum_i wkp[j,i] q[i]
    #pragma unroll 8
    for (int i = 0; i < D; i++) acc = fmaf(wkp[j * D + i], qv[i], acc);
    av[j] = acc;
    __syncthreads();

    float u = 0.0f;                    // u_j = sum_i wx2[j,i] a[i]
    #pragma unroll 8
    for (int i = 0; i < D; i++) u = fmaf(wx2[j * D + i], av[i], u);

    const float scale = 0.08838834764831845f;   // 128^-0.5
    g_u[b * D + j] = u * scale;

    red[j] = bx2[j] * av[j] + qv[j] * bkp[j];
    __syncthreads();
    for (int s = 64; s > 0; s >>= 1) {
        if (j < s) red[j] += red[j + s];
        __syncthreads();
    }
    if (j == 0) g_const[b] = red[0] * scale;
}

// ---------------- pass 1: scores[b,n] = gelu(x@wx1+bx1) . u[b] + c[b] ----------------
// 2 items per thread: 8 FFMA per broadcast LDS.128 of the weight tile.
__global__ void __launch_bounds__(256) pass1_kernel(const float* __restrict__ x_items,
                                                    const float* __restrict__ wx1,
                                                    const float* __restrict__ bx1) {
    __shared__ float ws[IDIM * D];   // 32 KB weight tile
    __shared__ float bs[D];
    __shared__ float us[D];

    int b = blockIdx.y;
    int t = threadIdx.x;
    int n0 = blockIdx.x * 512 + t;
    int n1 = n0 + 256;

    for (int k = t; k < IDIM * D; k += 256) ws[k] = wx1[k];
    if (t < D) { bs[t] = bx1[t]; us[t] = g_u[b * D + t]; }
    __syncthreads();

    const float4* xp0 = (const float4*)(x_items + ((size_t)b * NITEMS + (size_t)n0) * IDIM);
    const float4* xp1 = (const float4*)(x_items + ((size_t)b * NITEMS + (size_t)n1) * IDIM);
    float xr0[IDIM], xr1[IDIM];
    #pragma unroll
    for (int k = 0; k < 16; k++) {
        float4 v = xp0[k];
        xr0[4 * k + 0] = v.x; xr0[4 * k + 1] = v.y;
        xr0[4 * k + 2] = v.z; xr0[4 * k + 3] = v.w;
        float4 w = xp1[k];
        xr1[4 * k + 0] = w.x; xr1[4 * k + 1] = w.y;
        xr1[4 * k + 2] = w.z; xr1[4 * k + 3] = w.w;
    }

    float cb = g_const[b];
    float s0 = cb, s1 = cb;
    #pragma unroll 1
    for (int j = 0; j < D; j += 4) {
        float a0 = bs[j], a1 = bs[j + 1], a2 = bs[j + 2], a3 = bs[j + 3];
        float c0 = a0,    c1 = a1,        c2 = a2,        c3 = a3;
        #pragma unroll
        for (int i = 0; i < IDIM; i++) {
            float4 w = *(const float4*)&ws[i * D + j];   // broadcast LDS.128
            float x0 = xr0[i], x1 = xr1[i];
            a0 = fmaf(x0, w.x, a0); a1 = fmaf(x0, w.y, a1);
            a2 = fmaf(x0, w.z, a2); a3 = fmaf(x0, w.w, a3);
            c0 = fmaf(x1, w.x, c0); c1 = fmaf(x1, w.y, c1);
            c2 = fmaf(x1, w.z, c2); c3 = fmaf(x1, w.w, c3);
        }
        float u0 = us[j], u1 = us[j + 1], u2 = us[j + 2], u3 = us[j + 3];
        s0 = fmaf(gelu_f(a0), u0, s0); s0 = fmaf(gelu_f(a1), u1, s0);
        s0 = fmaf(gelu_f(a2), u2, s0); s0 = fmaf(gelu_f(a3), u3, s0);
        s1 = fmaf(gelu_f(c0), u0, s1); s1 = fmaf(gelu_f(c1), u1, s1);
        s1 = fmaf(gelu_f(c2), u2, s1); s1 = fmaf(gelu_f(c3), u3, s1);
    }
    g_scores[b * NITEMS + n0] = s0;
    g_scores[b * NITEMS + n1] = s1;
}

// ---------------- bisection for sparsemax tau (register-resident) ----------------
__global__ void __launch_bounds__(512) bisect_kernel() {
    int b = blockIdx.x;
    int t = threadIdx.x;
    int w = t >> 5, l = t & 31;

    const float* sc = g_scores + b * NITEMS;
    float z[32];
    #pragma unroll
    for (int k = 0; k < 32; k++) z[k] = sc[t + k * 512];

    // block max
    float m = z[0];
    #pragma unroll
    for (int k = 1; k < 32; k++) m = fmaxf(m, z[k]);
    __shared__ float red[16];
    __shared__ float sh_flag;
    #pragma unroll
    for (int o = 16; o > 0; o >>= 1) m = fmaxf(m, __shfl_xor_sync(0xffffffffu, m, o));
    if (l == 0) red[w] = m;
    __syncthreads();
    if (t == 0) {
        float v = red[0];
        for (int i = 1; i < 16; i++) v = fmaxf(v, red[i]);
        red[0] = v;
    }
    __syncthreads();
    float zmax = red[0];
    __syncthreads();

    float lo = zmax - 1.0f, hi = zmax;
    for (int it = 0; it < 40; it++) {
        float mid = 0.5f * (lo + hi);
        float s = 0.0f;
        #pragma unroll
        for (int k = 0; k < 32; k++) s += fmaxf(z[k] - mid, 0.0f);
        #pragma unroll
        for (int o = 16; o > 0; o >>= 1) s += __shfl_xor_sync(0xffffffffu, s, o);
        __syncthreads();
        if (l == 0) red[w] = s;
        __syncthreads();
        if (t == 0) {
            float v = 0.0f;
            for (int i = 0; i < 16; i++) v += red[i];
            sh_flag = (v >= 1.0f) ? 1.0f : 0.0f;
        }
        __syncthreads();
        if (sh_flag > 0.5f) lo = mid; else hi = mid;
    }

    float tau = 0.5f * (lo + hi);
    float s = 0.0f;
    #pragma unroll
    for (int k = 0; k < 32; k++) s += fmaxf(z[k] - tau, 0.0f);
    #pragma unroll
    for (int o = 16; o > 0; o >>= 1) s += __shfl_xor_sync(0xffffffffu, s, o);
    __syncthreads();
    if (l == 0) red[w] = s;
    __syncthreads();
    if (t == 0) {
        float v = 0.0f;
        for (int i = 0; i < 16; i++) v += red[i];
        g_tau[b] = tau;
        g_asum[b] = v;
    }
}

// ---------------- pass 2 + fused finalize (last block) ----------------
__global__ void __launch_bounds__(256) pass2_kernel(const float* __restrict__ x_items,
                                                    const float* __restrict__ wx1,
                                                    const float* __restrict__ bx1,
                                                    float* __restrict__ out,
                                                    const float* __restrict__ wx2, const float* __restrict__ bx2,
                                                    const float* __restrict__ wvp, const float* __restrict__ bvp,
                                                    const float* __restrict__ wp1, const float* __restrict__ bp1,
                                                    const float* __restrict__ wp2, const float* __restrict__ bp2) {
    int b = blockIdx.y;
    int t = threadIdx.x;
    int n = blockIdx.x * 256 + t;

    float tau = g_tau[b];
    float wgt = g_scores[b * NITEMS + n] - tau;
    int any = __syncthreads_or(wgt > 0.0f);

    if (any) {   // rare: sparsemax support is tiny
        __shared__ float ws[IDIM * D];
        __shared__ float bsx[D];
        for (int k = t; k < IDIM * D; k += 256) ws[k] = wx1[k];
        if (t < D) bsx[t] = bx1[t];
        __syncthreads();

        if (wgt > 0.0f) {
            const float4* xp = (const float4*)(x_items + ((size_t)b * NITEMS + (size_t)n) * IDIM);
            float xr[IDIM];
            #pragma unroll
            for (int k = 0; k < 16; k++) {
                float4 v = xp[k];
                xr[4 * k + 0] = v.x; xr[4 * k + 1] = v.y;
                xr[4 * k + 2] = v.z; xr[4 * k + 3] = v.w;
            }
            #pragma unroll 1
            for (int j = 0; j < D; j++) {
                float a = bsx[j];
                #pragma unroll
                for (int i = 0; i < IDIM; i++) a = fmaf(xr[i], ws[i * D + j], a);
                atomicAdd(&g_sacc[b * D + j], wgt * gelu_f(a));
            }
        }
    }

    // ---- last-block-done detection ----
    __threadfence();
    __shared__ unsigned int lastflag;
    if (t == 0) {
        unsigned int r = atomicAdd(&g_done, 1u);
        lastflag = (r == (unsigned)(gridDim.x * gridDim.y) - 1u) ? 1u : 0u;
    }
    __syncthreads();
    if (!lastflag) return;

    // ---- finalize: 2 batches in parallel (half-block each), 16 iterations ----
    __shared__ float sn[2][D], hb[2][D], zz[2][D], pp[2][D];
    int half = t >> 7;       // 0 or 1
    int j = t & 127;
    for (int k = 0; k < B / 2; k++) {
        int bb = 2 * k + half;
        sn[half][j] = g_sacc[bb * D + j] / g_asum[bb];
        __syncthreads();

        float acc = bx2[j];
        #pragma unroll 8
        for (int i = 0; i < D; i++) acc = fmaf(sn[half][i], wx2[i * D + j], acc);
        hb[half][j] = acc;
        __syncthreads();

        acc = bvp[j];
        #pragma unroll 8
        for (int i = 0; i < D; i++) acc = fmaf(hb[half][i], wvp[i * D + j], acc);
        zz[half][j] = acc;
        __syncthreads();

        acc = bp1[j];
        #pragma unroll 8
        for (int i = 0; i < D; i++) acc = fmaf(zz[half][i], wp1[i * D + j], acc);
        pp[half][j] = gelu_f(acc);
        __syncthreads();

        if (j < 10) {
            acc = bp2[j];
            #pragma unroll 8
            for (int i = 0; i < D; i++) acc = fmaf(pp[half][i], wp2[i * 10 + j], acc);
            out[bb * 10 + j] = acc;
        }
        __syncthreads();
    }
}

// ---------------- launch (exactly 4 kernels -> ncu -s 5 lands on pass1) ----------------
extern "C" void kernel_launch(void* const* d_in, const int* in_sizes, int n_in,
                              void* d_out, int out_size) {
    const float* x_items = (const float*)d_in[0];
    const float* x_query = (const float*)d_in[1];
    const float* wx1 = (const float*)d_in[2];  const float* bx1 = (const float*)d_in[3];
    const float* wx2 = (const float*)d_in[4];  const float* bx2 = (const float*)d_in[5];
    const float* wq1 = (const float*)d_in[6];  const float* bq1 = (const float*)d_in[7];
    const float* wq2 = (const float*)d_in[8];  const float* bq2 = (const float*)d_in[9];
    const float* wqp = (const float*)d_in[10]; const float* bqp = (const float*)d_in[11];
    const float* wkp = (const float*)d_in[12]; const float* bkp = (const float*)d_in[13];
    const float* wvp = (const float*)d_in[14]; const float* bvp = (const float*)d_in[15];
    const float* wp1 = (const float*)d_in[16]; const float* bp1 = (const float*)d_in[17];
    const float* wp2 = (const float*)d_in[18]; const float* bp2 = (const float*)d_in[19];
    float* out = (float*)d_out;

    prep_kernel<<<B, D>>>(x_query, wq1, bq1, wq2, bq2, wqp, bqp, wkp, bkp, wx2, bx2);
    dim3 grid1(NITEMS / 512, B);
    pass1_kernel<<<grid1, 256>>>(x_items, wx1, bx1);
    bisect_kernel<<<B, 512>>>();
    dim3 grid2(NITEMS / 256, B);
    pass2_kernel<<<grid2, 256>>>(x_items, wx1, bx1, out,
                                 wx2, bx2, wvp, bvp, wp1, bp1, wp2, bp2);
}

// round 5
// speedup vs baseline: 1.6146x; 1.6146x over previous
#include <cuda_runtime.h>
#include <math.h>

#define B      32
#define NITEMS 16384
#define D      128
#define IDIM   64

// ---------------- device scratch (no allocation allowed) ----------------
__device__ float g_scores[B * NITEMS];   // 2 MB, fits L2
__device__ float g_u[B * D];             // per-batch score vector (scale folded in)
__device__ float g_const[B];             // per-batch score constant (scale folded in)
__device__ float g_tau[B];
__device__ float g_asum[B];              // sum of relu(z - tau)
__device__ float g_sacc[B * D];          // sum_n relu(score-tau) * g[b,n]

// Branch-free erf-gelu: Abramowitz-Stegun 7.1.26, |abs err| <= 1.5e-7 on erf.
__device__ __forceinline__ float gelu_f(float x) {
    float ax = fabsf(x) * 0.7071067811865476f;          // |x|/sqrt(2)
    float t  = __fdividef(1.0f, fmaf(0.3275911f, ax, 1.0f));
    float p  = t * fmaf(t, fmaf(t, fmaf(t, fmaf(t, 1.061405429f, -1.453152027f),
                                        1.421413741f), -0.284496736f), 0.254829592f);
    float e  = __expf(-ax * ax);
    float erf_ax = fmaf(-p, e, 1.0f);                   // erf(|x|/sqrt(2))
    return 0.5f * x * (1.0f + copysignf(erf_ax, x));
}

// ---------------- prep: per-batch query path + folded vectors + init ----------------
// u[b]  = scale * wx2 @ (wkp @ q[b])
// c[b]  = scale * (bx2 . (wkp @ q[b]) + q[b] . bkp)
__global__ void prep_kernel(const float* __restrict__ x_query,
                            const float* __restrict__ wq1, const float* __restrict__ bq1,
                            const float* __restrict__ wq2, const float* __restrict__ bq2,
                            const float* __restrict__ wqp, const float* __restrict__ bqp,
                            const float* __restrict__ wkp, const float* __restrict__ bkp,
                            const float* __restrict__ wx2, const float* __restrict__ bx2) {
    int b = blockIdx.x;
    int j = threadIdx.x;
    __shared__ float h1[D], hq[D], qv[D], av[D], red[D];

    g_sacc[b * D + j] = 0.0f;            // fused init

    float xq = x_query[b];
    h1[j] = gelu_f(fmaf(xq, wq1[j], bq1[j]));
    __syncthreads();

    float acc = bq2[j];
    #pragma unroll 8
    for (int i = 0; i < D; i++) acc = fmaf(h1[i], wq2[i * D + j], acc);
    hq[j] = acc;
    __syncthreads();

    acc = bqp[j];
    #pragma unroll 8
    for (int i = 0; i < D; i++) acc = fmaf(hq[i], wqp[i * D + j], acc);
    qv[j] = acc;                       // q[b][j]
    __syncthreads();

    acc = 0.0f;                        // a = wkp @ q : a_j = sum_i wkp[j,i] q[i]
    #pragma unroll 8
    for (int i = 0; i < D; i++) acc = fmaf(wkp[j * D + i], qv[i], acc);
    av[j] = acc;
    __syncthreads();

    float u = 0.0f;                    // u_j = sum_i wx2[j,i] a[i]
    #pragma unroll 8
    for (int i = 0; i < D; i++) u = fmaf(wx2[j * D + i], av[i], u);

    const float scale = 0.08838834764831845f;   // 128^-0.5
    g_u[b * D + j] = u * scale;

    red[j] = bx2[j] * av[j] + qv[j] * bkp[j];
    __syncthreads();
    for (int s = 64; s > 0; s >>= 1) {
        if (j < s) red[j] += red[j + s];
        __syncthreads();
    }
    if (j == 0) g_const[b] = red[0] * scale;
}

// ---------------- pass 1: scores[b,n] = gelu(x@wx1+bx1) . u[b] + c[b] ----------------
// 2 items per thread: 8 FFMA per broadcast LDS.128 of the weight tile.
__global__ void __launch_bounds__(256) pass1_kernel(const float* __restrict__ x_items,
                                                    const float* __restrict__ wx1,
                                                    const float* __restrict__ bx1) {
    __shared__ float ws[IDIM * D];   // 32 KB weight tile
    __shared__ float bs[D];
    __shared__ float us[D];

    int b = blockIdx.y;
    int t = threadIdx.x;
    int n0 = blockIdx.x * 512 + t;
    int n1 = n0 + 256;

    for (int k = t; k < IDIM * D; k += 256) ws[k] = wx1[k];
    if (t < D) { bs[t] = bx1[t]; us[t] = g_u[b * D + t]; }
    __syncthreads();

    const float4* xp0 = (const float4*)(x_items + ((size_t)b * NITEMS + (size_t)n0) * IDIM);
    const float4* xp1 = (const float4*)(x_items + ((size_t)b * NITEMS + (size_t)n1) * IDIM);
    float xr0[IDIM], xr1[IDIM];
    #pragma unroll
    for (int k = 0; k < 16; k++) {
        float4 v = xp0[k];
        xr0[4 * k + 0] = v.x; xr0[4 * k + 1] = v.y;
        xr0[4 * k + 2] = v.z; xr0[4 * k + 3] = v.w;
        float4 w = xp1[k];
        xr1[4 * k + 0] = w.x; xr1[4 * k + 1] = w.y;
        xr1[4 * k + 2] = w.z; xr1[4 * k + 3] = w.w;
    }

    float cb = g_const[b];
    float s0 = cb, s1 = cb;
    #pragma unroll 1
    for (int j = 0; j < D; j += 4) {
        float a0 = bs[j], a1 = bs[j + 1], a2 = bs[j + 2], a3 = bs[j + 3];
        float c0 = a0,    c1 = a1,        c2 = a2,        c3 = a3;
        #pragma unroll
        for (int i = 0; i < IDIM; i++) {
            float4 w = *(const float4*)&ws[i * D + j];   // broadcast LDS.128
            float x0 = xr0[i], x1 = xr1[i];
            a0 = fmaf(x0, w.x, a0); a1 = fmaf(x0, w.y, a1);
            a2 = fmaf(x0, w.z, a2); a3 = fmaf(x0, w.w, a3);
            c0 = fmaf(x1, w.x, c0); c1 = fmaf(x1, w.y, c1);
            c2 = fmaf(x1, w.z, c2); c3 = fmaf(x1, w.w, c3);
        }
        float u0 = us[j], u1 = us[j + 1], u2 = us[j + 2], u3 = us[j + 3];
        s0 = fmaf(gelu_f(a0), u0, s0); s0 = fmaf(gelu_f(a1), u1, s0);
        s0 = fmaf(gelu_f(a2), u2, s0); s0 = fmaf(gelu_f(a3), u3, s0);
        s1 = fmaf(gelu_f(c0), u0, s1); s1 = fmaf(gelu_f(c1), u1, s1);
        s1 = fmaf(gelu_f(c2), u2, s1); s1 = fmaf(gelu_f(c3), u3, s1);
    }
    g_scores[b * NITEMS + n0] = s0;
    g_scores[b * NITEMS + n1] = s1;
}

// ---------------- bisection for sparsemax tau (register-resident) ----------------
__global__ void __launch_bounds__(512) bisect_kernel() {
    int b = blockIdx.x;
    int t = threadIdx.x;
    int w = t >> 5, l = t & 31;

    const float* sc = g_scores + b * NITEMS;
    float z[32];
    #pragma unroll
    for (int k = 0; k < 32; k++) z[k] = sc[t + k * 512];

    // block max
    float m = z[0];
    #pragma unroll
    for (int k = 1; k < 32; k++) m = fmaxf(m, z[k]);
    __shared__ float red[16];
    __shared__ float sh_flag;
    #pragma unroll
    for (int o = 16; o > 0; o >>= 1) m = fmaxf(m, __shfl_xor_sync(0xffffffffu, m, o));
    if (l == 0) red[w] = m;
    __syncthreads();
    if (t == 0) {
        float v = red[0];
        for (int i = 1; i < 16; i++) v = fmaxf(v, red[i]);
        red[0] = v;
    }
    __syncthreads();
    float zmax = red[0];
    __syncthreads();

    float lo = zmax - 1.0f, hi = zmax;
    for (int it = 0; it < 40; it++) {
        float mid = 0.5f * (lo + hi);
        float s = 0.0f;
        #pragma unroll
        for (int k = 0; k < 32; k++) s += fmaxf(z[k] - mid, 0.0f);
        #pragma unroll
        for (int o = 16; o > 0; o >>= 1) s += __shfl_xor_sync(0xffffffffu, s, o);
        __syncthreads();
        if (l == 0) red[w] = s;
        __syncthreads();
        if (t == 0) {
            float v = 0.0f;
            for (int i = 0; i < 16; i++) v += red[i];
            sh_flag = (v >= 1.0f) ? 1.0f : 0.0f;
        }
        __syncthreads();
        if (sh_flag > 0.5f) lo = mid; else hi = mid;
    }

    float tau = 0.5f * (lo + hi);
    float s = 0.0f;
    #pragma unroll
    for (int k = 0; k < 32; k++) s += fmaxf(z[k] - tau, 0.0f);
    #pragma unroll
    for (int o = 16; o > 0; o >>= 1) s += __shfl_xor_sync(0xffffffffu, s, o);
    __syncthreads();
    if (l == 0) red[w] = s;
    __syncthreads();
    if (t == 0) {
        float v = 0.0f;
        for (int i = 0; i < 16; i++) v += red[i];
        g_tau[b] = tau;
        g_asum[b] = v;
    }
}

// ---------------- pass 2: s[b] = sum over support of (score - tau) * g[b,n] ----------------
__global__ void __launch_bounds__(256) pass2_kernel(const float* __restrict__ x_items,
                                                    const float* __restrict__ wx1,
                                                    const float* __restrict__ bx1) {
    int b = blockIdx.y;
    int t = threadIdx.x;
    int n = blockIdx.x * 256 + t;

    float tau = g_tau[b];
    float wgt = g_scores[b * NITEMS + n] - tau;
    int any = __syncthreads_or(wgt > 0.0f);
    if (!any) return;   // vast majority of blocks: sparsemax support is tiny

    __shared__ float ws[IDIM * D];
    __shared__ float bs[D];
    for (int k = t; k < IDIM * D; k += 256) ws[k] = wx1[k];
    if (t < D) bs[t] = bx1[t];
    __syncthreads();

    if (wgt > 0.0f) {
        const float4* xp = (const float4*)(x_items + ((size_t)b * NITEMS + (size_t)n) * IDIM);
        float xr[IDIM];
        #pragma unroll
        for (int k = 0; k < 16; k++) {
            float4 v = xp[k];
            xr[4 * k + 0] = v.x; xr[4 * k + 1] = v.y;
            xr[4 * k + 2] = v.z; xr[4 * k + 3] = v.w;
        }
        #pragma unroll 1
        for (int j = 0; j < D; j++) {
            float a = bs[j];
            #pragma unroll
            for (int i = 0; i < IDIM; i++) a = fmaf(xr[i], ws[i * D + j], a);
            atomicAdd(&g_sacc[b * D + j], wgt * gelu_f(a));
        }
    }
}

// ---------------- finalize: z -> output MLP (32 parallel blocks) ----------------
__global__ void finalize_kernel(float* __restrict__ out,
                                const float* __restrict__ wx2, const float* __restrict__ bx2,
                                const float* __restrict__ wvp, const float* __restrict__ bvp,
                                const float* __restrict__ wp1, const float* __restrict__ bp1,
                                const float* __restrict__ wp2, const float* __restrict__ bp2) {
    int b = blockIdx.x;
    int j = threadIdx.x;
    __shared__ float sn[D], hb[D], zz[D], pp[D];

    sn[j] = g_sacc[b * D + j] / g_asum[b];     // normalized attn-weighted g sum
    __syncthreads();

    float acc = bx2[j];
    #pragma unroll 8
    for (int i = 0; i < D; i++) acc = fmaf(sn[i], wx2[i * D + j], acc);
    hb[j] = acc;
    __syncthreads();

    acc = bvp[j];
    #pragma unroll 8
    for (int i = 0; i < D; i++) acc = fmaf(hb[i], wvp[i * D + j], acc);
    zz[j] = acc;
    __syncthreads();

    acc = bp1[j];
    #pragma unroll 8
    for (int i = 0; i < D; i++) acc = fmaf(zz[i], wp1[i * D + j], acc);
    pp[j] = gelu_f(acc);
    __syncthreads();

    if (j < 10) {
        acc = bp2[j];
        #pragma unroll 8
        for (int i = 0; i < D; i++) acc = fmaf(pp[i], wp2[i * 10 + j], acc);
        out[b * 10 + j] = acc;
    }
}

// ---------------- launch ----------------
extern "C" void kernel_launch(void* const* d_in, const int* in_sizes, int n_in,
                              void* d_out, int out_size) {
    const float* x_items = (const float*)d_in[0];
    const float* x_query = (const float*)d_in[1];
    const float* wx1 = (const float*)d_in[2];  const float* bx1 = (const float*)d_in[3];
    const float* wx2 = (const float*)d_in[4];  const float* bx2 = (const float*)d_in[5];
    const float* wq1 = (const float*)d_in[6];  const float* bq1 = (const float*)d_in[7];
    const float* wq2 = (const float*)d_in[8];  const float* bq2 = (const float*)d_in[9];
    const float* wqp = (const float*)d_in[10]; const float* bqp = (const float*)d_in[11];
    const float* wkp = (const float*)d_in[12]; const float* bkp = (const float*)d_in[13];
    const float* wvp = (const float*)d_in[14]; const float* bvp = (const float*)d_in[15];
    const float* wp1 = (const float*)d_in[16]; const float* bp1 = (const float*)d_in[17];
    const float* wp2 = (const float*)d_in[18]; const float* bp2 = (const float*)d_in[19];
    float* out = (float*)d_out;

    prep_kernel<<<B, D>>>(x_query, wq1, bq1, wq2, bq2, wqp, bqp, wkp, bkp, wx2, bx2);
    dim3 grid1(NITEMS / 512, B);
    pass1_kernel<<<grid1, 256>>>(x_items, wx1, bx1);
    bisect_kernel<<<B, 512>>>();
    dim3 grid2(NITEMS / 256, B);
    pass2_kernel<<<grid2, 256>>>(x_items, wx1, bx1);
    finalize_kernel<<<B, D>>>(out, wx2, bx2, wvp, bvp, wp1, bp1, wp2, bp2);
}

// round 7
// speedup vs baseline: 2.5214x; 1.5616x over previous
#include <cuda_runtime.h>
#include <math.h>

#define B      32
#define NITEMS 16384
#define D      128
#define IDIM   64

// ---------------- device scratch (no allocation allowed) ----------------
__device__ float g_scores[B * NITEMS];   // 2 MB, fits L2
__device__ float g_u[B * D];             // per-batch score vector (scale folded in)
__device__ float g_const[B];             // per-batch score constant (scale folded in)
__device__ float g_asum[B];              // sum of relu(z - tau)
__device__ float g_sacc[B * D];          // sum_n relu(score-tau) * g[b,n]
__device__ int   g_supp[B * NITEMS];     // compacted support indices
__device__ float g_swgt[B * NITEMS];     // compacted support weights (z - tau)
__device__ int   g_cnt[B];               // support count per batch

// Branch-free erf-gelu: Abramowitz-Stegun 7.1.26, |abs err| <= 1.5e-7 on erf.
__device__ __forceinline__ float gelu_f(float x) {
    float ax = fabsf(x) * 0.7071067811865476f;          // |x|/sqrt(2)
    float t  = __fdividef(1.0f, fmaf(0.3275911f, ax, 1.0f));
    float p  = t * fmaf(t, fmaf(t, fmaf(t, fmaf(t, 1.061405429f, -1.453152027f),
                                        1.421413741f), -0.284496736f), 0.254829592f);
    float e  = __expf(-ax * ax);
    float erf_ax = fmaf(-p, e, 1.0f);                   // erf(|x|/sqrt(2))
    return 0.5f * x * (1.0f + copysignf(erf_ax, x));
}

// ---------------- prep: per-batch query path + folded vectors + init ----------------
// u[b]  = scale * wx2 @ (wkp @ q[b])
// c[b]  = scale * (bx2 . (wkp @ q[b]) + q[b] . bkp)
__global__ void prep_kernel(const float* __restrict__ x_query,
                            const float* __restrict__ wq1, const float* __restrict__ bq1,
                            const float* __restrict__ wq2, const float* __restrict__ bq2,
                            const float* __restrict__ wqp, const float* __restrict__ bqp,
                            const float* __restrict__ wkp, const float* __restrict__ bkp,
                            const float* __restrict__ wx2, const float* __restrict__ bx2) {
    int b = blockIdx.x;
    int j = threadIdx.x;
    __shared__ float h1[D], hq[D], qv[D], av[D], red[D];

    g_sacc[b * D + j] = 0.0f;            // fused init

    float xq = x_query[b];
    h1[j] = gelu_f(fmaf(xq, wq1[j], bq1[j]));
    __syncthreads();

    float acc = bq2[j];
    #pragma unroll 8
    for (int i = 0; i < D; i++) acc = fmaf(h1[i], wq2[i * D + j], acc);
    hq[j] = acc;
    __syncthreads();

    acc = bqp[j];
    #pragma unroll 8
    for (int i = 0; i < D; i++) acc = fmaf(hq[i], wqp[i * D + j], acc);
    qv[j] = acc;                       // q[b][j]
    __syncthreads();

    acc = 0.0f;                        // a = wkp @ q : a_j = sum_i wkp[j,i] q[i]
    #pragma unroll 8
    for (int i = 0; i < D; i++) acc = fmaf(wkp[j * D + i], qv[i], acc);
    av[j] = acc;
    __syncthreads();

    float u = 0.0f;                    // u_j = sum_i wx2[j,i] a[i]
    #pragma unroll 8
    for (int i = 0; i < D; i++) u = fmaf(wx2[j * D + i], av[i], u);

    const float scale = 0.08838834764831845f;   // 128^-0.5
    g_u[b * D + j] = u * scale;

    red[j] = bx2[j] * av[j] + qv[j] * bkp[j];
    __syncthreads();
    for (int s = 64; s > 0; s >>= 1) {
        if (j < s) red[j] += red[j + s];
        __syncthreads();
    }
    if (j == 0) g_const[b] = red[0] * scale;
}

// ---------------- pass 1: scores[b,n] = gelu(x@wx1+bx1) . u[b] + c[b] ----------------
// 2 items per thread: 8 FFMA per broadcast LDS.128 of the weight tile.
__global__ void __launch_bounds__(256) pass1_kernel(const float* __restrict__ x_items,
                                                    const float* __restrict__ wx1,
                                                    const float* __restrict__ bx1) {
    __shared__ float ws[IDIM * D];   // 32 KB weight tile
    __shared__ float bs[D];
    __shared__ float us[D];

    int b = blockIdx.y;
    int t = threadIdx.x;
    int n0 = blockIdx.x * 512 + t;
    int n1 = n0 + 256;

    for (int k = t; k < IDIM * D; k += 256) ws[k] = wx1[k];
    if (t < D) { bs[t] = bx1[t]; us[t] = g_u[b * D + t]; }
    __syncthreads();

    const float4* xp0 = (const float4*)(x_items + ((size_t)b * NITEMS + (size_t)n0) * IDIM);
    const float4* xp1 = (const float4*)(x_items + ((size_t)b * NITEMS + (size_t)n1) * IDIM);
    float xr0[IDIM], xr1[IDIM];
    #pragma unroll
    for (int k = 0; k < 16; k++) {
        float4 v = xp0[k];
        xr0[4 * k + 0] = v.x; xr0[4 * k + 1] = v.y;
        xr0[4 * k + 2] = v.z; xr0[4 * k + 3] = v.w;
        float4 w = xp1[k];
        xr1[4 * k + 0] = w.x; xr1[4 * k + 1] = w.y;
        xr1[4 * k + 2] = w.z; xr1[4 * k + 3] = w.w;
    }

    float cb = g_const[b];
    float s0 = cb, s1 = cb;
    #pragma unroll 1
    for (int j = 0; j < D; j += 4) {
        float a0 = bs[j], a1 = bs[j + 1], a2 = bs[j + 2], a3 = bs[j + 3];
        float c0 = a0,    c1 = a1,        c2 = a2,        c3 = a3;
        #pragma unroll
        for (int i = 0; i < IDIM; i++) {
            float4 w = *(const float4*)&ws[i * D + j];   // broadcast LDS.128
            float x0 = xr0[i], x1 = xr1[i];
            a0 = fmaf(x0, w.x, a0); a1 = fmaf(x0, w.y, a1);
            a2 = fmaf(x0, w.z, a2); a3 = fmaf(x0, w.w, a3);
            c0 = fmaf(x1, w.x, c0); c1 = fmaf(x1, w.y, c1);
            c2 = fmaf(x1, w.z, c2); c3 = fmaf(x1, w.w, c3);
        }
        float u0 = us[j], u1 = us[j + 1], u2 = us[j + 2], u3 = us[j + 3];
        s0 = fmaf(gelu_f(a0), u0, s0); s0 = fmaf(gelu_f(a1), u1, s0);
        s0 = fmaf(gelu_f(a2), u2, s0); s0 = fmaf(gelu_f(a3), u3, s0);
        s1 = fmaf(gelu_f(c0), u0, s1); s1 = fmaf(gelu_f(c1), u1, s1);
        s1 = fmaf(gelu_f(c2), u2, s1); s1 = fmaf(gelu_f(c3), u3, s1);
    }
    g_scores[b * NITEMS + n0] = s0;
    g_scores[b * NITEMS + n1] = s1;
}

// ---------------- bisection for sparsemax tau + support compaction ----------------
__global__ void __launch_bounds__(512) bisect_kernel() {
    int b = blockIdx.x;
    int t = threadIdx.x;
    int w = t >> 5, l = t & 31;

    const float* sc = g_scores + b * NITEMS;
    float z[32];
    #pragma unroll
    for (int k = 0; k < 32; k++) z[k] = sc[t + k * 512];

    // block max
    float m = z[0];
    #pragma unroll
    for (int k = 1; k < 32; k++) m = fmaxf(m, z[k]);
    __shared__ float red[16];
    __shared__ float sh_flag;
    __shared__ int   sh_cnt;
    #pragma unroll
    for (int o = 16; o > 0; o >>= 1) m = fmaxf(m, __shfl_xor_sync(0xffffffffu, m, o));
    if (l == 0) red[w] = m;
    __syncthreads();
    if (t == 0) {
        float v = red[0];
        for (int i = 1; i < 16; i++) v = fmaxf(v, red[i]);
        red[0] = v;
        sh_cnt = 0;
    }
    __syncthreads();
    float zmax = red[0];
    __syncthreads();

    float lo = zmax - 1.0f, hi = zmax;
    for (int it = 0; it < 40; it++) {
        float mid = 0.5f * (lo + hi);
        float s = 0.0f;
        #pragma unroll
        for (int k = 0; k < 32; k++) s += fmaxf(z[k] - mid, 0.0f);
        #pragma unroll
        for (int o = 16; o > 0; o >>= 1) s += __shfl_xor_sync(0xffffffffu, s, o);
        __syncthreads();
        if (l == 0) red[w] = s;
        __syncthreads();
        if (t == 0) {
            float v = 0.0f;
            for (int i = 0; i < 16; i++) v += red[i];
            sh_flag = (v >= 1.0f) ? 1.0f : 0.0f;
        }
        __syncthreads();
        if (sh_flag > 0.5f) lo = mid; else hi = mid;
    }

    float tau = 0.5f * (lo + hi);
    float s = 0.0f;
    #pragma unroll
    for (int k = 0; k < 32; k++) s += fmaxf(z[k] - tau, 0.0f);
    #pragma unroll
    for (int o = 16; o > 0; o >>= 1) s += __shfl_xor_sync(0xffffffffu, s, o);
    __syncthreads();
    if (l == 0) red[w] = s;
    __syncthreads();
    if (t == 0) {
        float v = 0.0f;
        for (int i = 0; i < 16; i++) v += red[i];
        g_asum[b] = v;
    }

    // ---- compact the support set ----
    #pragma unroll
    for (int k = 0; k < 32; k++) {
        float d = z[k] - tau;
        if (d > 0.0f) {
            int pos = atomicAdd(&sh_cnt, 1);
            g_supp[b * NITEMS + pos] = t + k * 512;
            g_swgt[b * NITEMS + pos] = d;
        }
    }
    __syncthreads();
    if (t == 0) g_cnt[b] = sh_cnt;
}

// ---------------- pass 2: list-driven weighted g-sum over the support ----------------
// grid (8, B), 256 threads = 2 item-slots x 128 j-lanes.
__global__ void __launch_bounds__(256) pass2_kernel(const float* __restrict__ x_items,
                                                    const float* __restrict__ wx1,
                                                    const float* __restrict__ bx1) {
    int b    = blockIdx.y;
    int t    = threadIdx.x;
    int slot = t >> 7;         // 0 or 1
    int j    = t & 127;

    int cnt = g_cnt[b];
    int first = blockIdx.x * 2;             // this block's first list index
    if (first >= cnt) return;

    __shared__ float ws[IDIM * D];          // 32 KB weight tile
    __shared__ float bsx[D];
    __shared__ float xs[2][IDIM];
    for (int k = t; k < IDIM * D; k += 256) ws[k] = wx1[k];
    if (t < D) bsx[t] = bx1[t];

    float acc = 0.0f;
    for (int idx0 = first; idx0 < cnt; idx0 += 16) {
        int idx = idx0 + slot;
        int valid = (idx < cnt);
        int n = valid ? g_supp[b * NITEMS + idx] : 0;
        float wgt = valid ? g_swgt[b * NITEMS + idx] : 0.0f;

        __syncthreads();                    // xs reuse guard (also covers first-iter tile fill)
        if (j < IDIM) {
            xs[slot][j] = valid ? x_items[((size_t)b * NITEMS + (size_t)n) * IDIM + j] : 0.0f;
        }
        __syncthreads();

        float a = bsx[j];
        #pragma unroll
        for (int i = 0; i < IDIM; i++) a = fmaf(xs[slot][i], ws[i * D + j], a);
        acc = fmaf(wgt, gelu_f(a), acc);
    }
    atomicAdd(&g_sacc[b * D + j], acc);
}

// ---------------- finalize: z -> output MLP (32 parallel blocks) ----------------
__global__ void finalize_kernel(float* __restrict__ out,
                                const float* __restrict__ wx2, const float* __restrict__ bx2,
                                const float* __restrict__ wvp, const float* __restrict__ bvp,
                                const float* __restrict__ wp1, const float* __restrict__ bp1,
                                const float* __restrict__ wp2, const float* __restrict__ bp2) {
    int b = blockIdx.x;
    int j = threadIdx.x;
    __shared__ float sn[D], hb[D], zz[D], pp[D];

    sn[j] = g_sacc[b * D + j] / g_asum[b];     // normalized attn-weighted g sum
    __syncthreads();

    float acc = bx2[j];
    #pragma unroll 8
    for (int i = 0; i < D; i++) acc = fmaf(sn[i], wx2[i * D + j], acc);
    hb[j] = acc;
    __syncthreads();

    acc = bvp[j];
    #pragma unroll 8
    for (int i = 0; i < D; i++) acc = fmaf(hb[i], wvp[i * D + j], acc);
    zz[j] = acc;
    __syncthreads();

    acc = bp1[j];
    #pragma unroll 8
    for (int i = 0; i < D; i++) acc = fmaf(zz[i], wp1[i * D + j], acc);
    pp[j] = gelu_f(acc);
    __syncthreads();

    if (j < 10) {
        acc = bp2[j];
        #pragma unroll 8
        for (int i = 0; i < D; i++) acc = fmaf(pp[i], wp2[i * 10 + j], acc);
        out[b * 10 + j] = acc;
    }
}

// ---------------- launch ----------------
extern "C" void kernel_launch(void* const* d_in, const int* in_sizes, int n_in,
                              void* d_out, int out_size) {
    const float* x_items = (const float*)d_in[0];
    const float* x_query = (const float*)d_in[1];
    const float* wx1 = (const float*)d_in[2];  const float* bx1 = (const float*)d_in[3];
    const float* wx2 = (const float*)d_in[4];  const float* bx2 = (const float*)d_in[5];
    const float* wq1 = (const float*)d_in[6];  const float* bq1 = (const float*)d_in[7];
    const float* wq2 = (const float*)d_in[8];  const float* bq2 = (const float*)d_in[9];
    const float* wqp = (const float*)d_in[10]; const float* bqp = (const float*)d_in[11];
    const float* wkp = (const float*)d_in[12]; const float* bkp = (const float*)d_in[13];
    const float* wvp = (const float*)d_in[14]; const float* bvp = (const float*)d_in[15];
    const float* wp1 = (const float*)d_in[16]; const float* bp1 = (const float*)d_in[17];
    const float* wp2 = (const float*)d_in[18]; const float* bp2 = (const float*)d_in[19];
    float* out = (float*)d_out;

    prep_kernel<<<B, D>>>(x_query, wq1, bq1, wq2, bq2, wqp, bqp, wkp, bkp, wx2, bx2);
    dim3 grid1(NITEMS / 512, B);
    pass1_kernel<<<grid1, 256>>>(x_items, wx1, bx1);
    bisect_kernel<<<B, 512>>>();
    dim3 grid2(8, B);
    pass2_kernel<<<grid2, 256>>>(x_items, wx1, bx1);
    finalize_kernel<<<B, D>>>(out, wx2, bx2, wvp, bvp, wp1, bp1, wp2, bp2);
}

// round 13
// speedup vs baseline: 3.7572x; 1.4901x over previous
#include <cuda_runtime.h>
#include <cuda_bf16.h>
#include <cstdint>
#include <math.h>

#define B      32
#define NITEMS 16384
#define D      128
#define IDIM   64

// ---------------- device scratch (no allocation allowed) ----------------
__device__ float g_scores[B * NITEMS];
__device__ float g_u[B * D];
__device__ float g_const[B];
__device__ float g_asum[B];
__device__ float g_sacc[B * D];
__device__ int   g_supp[B * NITEMS];
__device__ float g_swgt[B * NITEMS];
__device__ int   g_cnt[B];
// Pre-packed B fragments for mma.sync m16n8k16 (row.col):
// index = ((part*4 + kc)*16 + nt)*32 + lane ; part 0 = w_hi, part 1 = w_lo
__device__ uint2 g_wfrag[2 * 4 * 16 * 32];

// Branch-free erf-gelu: Abramowitz-Stegun 7.1.26, |abs err| <= 1.5e-7 on erf.
__device__ __forceinline__ float gelu_f(float x) {
    float ax = fabsf(x) * 0.7071067811865476f;
    float t  = __fdividef(1.0f, fmaf(0.3275911f, ax, 1.0f));
    float p  = t * fmaf(t, fmaf(t, fmaf(t, fmaf(t, 1.061405429f, -1.453152027f),
                                        1.421413741f), -0.284496736f), 0.254829592f);
    float e  = __expf(-ax * ax);
    float erf_ax = fmaf(-p, e, 1.0f);
    return 0.5f * x * (1.0f + copysignf(erf_ax, x));
}

__device__ __forceinline__ uint32_t pack_bf16x2(float lo_val, float hi_val) {
    __nv_bfloat16 a = __float2bfloat16(lo_val);
    __nv_bfloat16 b = __float2bfloat16(hi_val);
    return (uint32_t)__bfloat16_as_ushort(a) | ((uint32_t)__bfloat16_as_ushort(b) << 16);
}

__device__ __forceinline__ void mma_bf16(float* c, const uint32_t* a, uint32_t b0, uint32_t b1) {
    asm volatile(
        "mma.sync.aligned.m16n8k16.row.col.f32.bf16.bf16.f32 "
        "{%0,%1,%2,%3}, {%4,%5,%6,%7}, {%8,%9}, {%0,%1,%2,%3};"
        : "+f"(c[0]), "+f"(c[1]), "+f"(c[2]), "+f"(c[3])
        : "r"(a[0]), "r"(a[1]), "r"(a[2]), "r"(a[3]), "r"(b0), "r"(b1));
}

// ---------------- prep_w: pack wx1 into per-lane mma B fragments ----------------
// B matrix for mma: B[k, n] = wx1[k*D + n] (k = input dim, n = output dim), col-major frag.
// Lane layout (m16n8k16): b0 = {B[k0, n], B[k0+1, n]}, b1 = {B[k0+8, n], B[k0+9, n]},
// k0 = kc*16 + (lane%4)*2, n = nt*8 + lane/4.
__global__ void prep_w_kernel(const float* __restrict__ wx1) {
    int idx  = blockIdx.x * 256 + threadIdx.x;   // 0..4095
    int lane = idx & 31;
    int nt   = (idx >> 5) & 15;
    int kc   = (idx >> 9) & 3;
    int part = idx >> 11;                        // 0 = hi, 1 = lo
    int n    = nt * 8 + (lane >> 2);
    int k0   = kc * 16 + (lane & 3) * 2;

    float w[4];
    int kk[4] = {k0, k0 + 1, k0 + 8, k0 + 9};
    #pragma unroll
    for (int i = 0; i < 4; i++) {
        float wv = wx1[kk[i] * D + n];
        __nv_bfloat16 hi = __float2bfloat16(wv);
        w[i] = part ? (wv - __bfloat162float(hi)) : wv;
    }
    uint2 fr;
    fr.x = pack_bf16x2(w[0], w[1]);
    fr.y = pack_bf16x2(w[2], w[3]);
    g_wfrag[idx] = fr;
}

// ---------------- prep: per-batch query path + folded vectors + init ----------------
__global__ void prep_kernel(const float* __restrict__ x_query,
                            const float* __restrict__ wq1, const float* __restrict__ bq1,
                            const float* __restrict__ wq2, const float* __restrict__ bq2,
                            const float* __restrict__ wqp, const float* __restrict__ bqp,
                            const float* __restrict__ wkp, const float* __restrict__ bkp,
                            const float* __restrict__ wx2, const float* __restrict__ bx2) {
    int b = blockIdx.x;
    int j = threadIdx.x;
    __shared__ float h1[D], hq[D], qv[D], av[D], red[D];

    g_sacc[b * D + j] = 0.0f;

    float xq = x_query[b];
    h1[j] = gelu_f(fmaf(xq, wq1[j], bq1[j]));
    __syncthreads();

    float acc = bq2[j];
    #pragma unroll 8
    for (int i = 0; i < D; i++) acc = fmaf(h1[i], wq2[i * D + j], acc);
    hq[j] = acc;
    __syncthreads();

    acc = bqp[j];
    #pragma unroll 8
    for (int i = 0; i < D; i++) acc = fmaf(hq[i], wqp[i * D + j], acc);
    qv[j] = acc;
    __syncthreads();

    acc = 0.0f;
    #pragma unroll 8
    for (int i = 0; i < D; i++) acc = fmaf(wkp[j * D + i], qv[i], acc);
    av[j] = acc;
    __syncthreads();

    float u = 0.0f;
    #pragma unroll 8
    for (int i = 0; i < D; i++) u = fmaf(wx2[j * D + i], av[i], u);

    const float scale = 0.08838834764831845f;
    g_u[b * D + j] = u * scale;

    red[j] = bx2[j] * av[j] + qv[j] * bkp[j];
    __syncthreads();
    for (int s = 64; s > 0; s >>= 1) {
        if (j < s) red[j] += red[j + s];
        __syncthreads();
    }
    if (j == 0) g_const[b] = red[0] * scale;
}

// ---------------- pass 1: mma.sync bf16x3 GEMM + gelu/dot epilogue ----------------
// Block: 8 warps x 16 items = 128 items. Per warp: 3 passes x 4 kchunks x 16 ntiles HMMA.
#define XS_STRIDE 68
__global__ void __launch_bounds__(256) pass1_mma_kernel(const float* __restrict__ x_items,
                                                        const float* __restrict__ bx1) {
    __shared__ float xs[128 * XS_STRIDE];
    __shared__ float bs[D], us[D];

    int t = threadIdx.x, warp = t >> 5, lane = t & 31;
    int b = blockIdx.y;
    int itemBase = blockIdx.x * 128;

    if (t < D) { bs[t] = bx1[t]; us[t] = g_u[b * D + t]; }

    // stage x tile [128 items][64] into padded smem (2 threads per row)
    {
        int row = t >> 1, half = t & 1;
        const float4* src = (const float4*)(x_items +
            ((size_t)b * NITEMS + (size_t)(itemBase + row)) * IDIM) + half * 8;
        float* dst = &xs[row * XS_STRIDE + half * 32];
        #pragma unroll
        for (int i = 0; i < 8; i++) *(float4*)(dst + i * 4) = src[i];
    }
    __syncthreads();

    // build A fragments (hi and lo) for 4 kchunks
    int r = warp * 16 + (lane >> 2);
    int kbase = (lane & 3) * 2;
    uint32_t ahi[4][4], alo[4][4];
    #pragma unroll
    for (int kc = 0; kc < 4; kc++) {
        int k0 = kc * 16 + kbase;
        float2 v00 = *(float2*)&xs[r * XS_STRIDE + k0];
        float2 v10 = *(float2*)&xs[(r + 8) * XS_STRIDE + k0];
        float2 v01 = *(float2*)&xs[r * XS_STRIDE + k0 + 8];
        float2 v11 = *(float2*)&xs[(r + 8) * XS_STRIDE + k0 + 8];
        float2 vv[4] = {v00, v10, v01, v11};
        #pragma unroll
        for (int i = 0; i < 4; i++) {
            __nv_bfloat16 hx = __float2bfloat16(vv[i].x);
            __nv_bfloat16 hy = __float2bfloat16(vv[i].y);
            ahi[kc][i] = (uint32_t)__bfloat16_as_ushort(hx) | ((uint32_t)__bfloat16_as_ushort(hy) << 16);
            alo[kc][i] = pack_bf16x2(vv[i].x - __bfloat162float(hx), vv[i].y - __bfloat162float(hy));
        }
    }

    float acc[16][4];
    #pragma unroll
    for (int nt = 0; nt < 16; nt++)
        #pragma unroll
        for (int i = 0; i < 4; i++) acc[nt][i] = 0.0f;

    // pass 0: x_hi * w_hi ; pass 1: x_lo * w_hi ; pass 2: x_hi * w_lo
    #pragma unroll
    for (int pass = 0; pass < 3; pass++) {
        int part = (pass == 2) ? 1 : 0;
        #pragma unroll
        for (int kc = 0; kc < 4; kc++) {
            const uint32_t* A = (pass == 1) ? alo[kc] : ahi[kc];
            const uint2* wf = &g_wfrag[((part * 4 + kc) * 16) * 32 + lane];
            #pragma unroll
            for (int nt = 0; nt < 16; nt++) {
                uint2 fr = wf[nt * 32];
                mma_bf16(acc[nt], A, fr.x, fr.y);
            }
        }
    }

    // epilogue: j = nt*8 + kbase + {0,1}; rows r (c0,c1) and r+8 (c2,c3)
    float s0 = 0.0f, s1 = 0.0f;
    #pragma unroll
    for (int nt = 0; nt < 16; nt++) {
        int j0 = nt * 8 + kbase;
        float u0 = us[j0], u1 = us[j0 + 1], b0 = bs[j0], b1 = bs[j0 + 1];
        s0 = fmaf(gelu_f(acc[nt][0] + b0), u0, s0);
        s0 = fmaf(gelu_f(acc[nt][1] + b1), u1, s0);
        s1 = fmaf(gelu_f(acc[nt][2] + b0), u0, s1);
        s1 = fmaf(gelu_f(acc[nt][3] + b1), u1, s1);
    }
    s0 += __shfl_xor_sync(0xffffffffu, s0, 1);
    s0 += __shfl_xor_sync(0xffffffffu, s0, 2);
    s1 += __shfl_xor_sync(0xffffffffu, s1, 1);
    s1 += __shfl_xor_sync(0xffffffffu, s1, 2);

    if ((lane & 3) == 0) {
        float cb = g_const[b];
        g_scores[b * NITEMS + itemBase + r]     = s0 + cb;
        g_scores[b * NITEMS + itemBase + r + 8] = s1 + cb;
    }
}

// ---------------- bisection for sparsemax tau + support compaction ----------------
__global__ void __launch_bounds__(512) bisect_kernel() {
    int b = blockIdx.x;
    int t = threadIdx.x;
    int w = t >> 5, l = t & 31;

    const float* sc = g_scores + b * NITEMS;
    float z[32];
    #pragma unroll
    for (int k = 0; k < 32; k++) z[k] = sc[t + k * 512];

    float m = z[0];
    #pragma unroll
    for (int k = 1; k < 32; k++) m = fmaxf(m, z[k]);
    __shared__ float red[16];
    __shared__ float sh_flag;
    __shared__ int   sh_cnt;
    #pragma unroll
    for (int o = 16; o > 0; o >>= 1) m = fmaxf(m, __shfl_xor_sync(0xffffffffu, m, o));
    if (l == 0) red[w] = m;
    __syncthreads();
    if (t == 0) {
        float v = red[0];
        for (int i = 1; i < 16; i++) v = fmaxf(v, red[i]);
        red[0] = v;
        sh_cnt = 0;
    }
    __syncthreads();
    float zmax = red[0];
    __syncthreads();

    float lo = zmax - 1.0f, hi = zmax;
    for (int it = 0; it < 40; it++) {
        float mid = 0.5f * (lo + hi);
        float s = 0.0f;
        #pragma unroll
        for (int k = 0; k < 32; k++) s += fmaxf(z[k] - mid, 0.0f);
        #pragma unroll
        for (int o = 16; o > 0; o >>= 1) s += __shfl_xor_sync(0xffffffffu, s, o);
        __syncthreads();
        if (l == 0) red[w] = s;
        __syncthreads();
        if (t == 0) {
            float v = 0.0f;
            for (int i = 0; i < 16; i++) v += red[i];
            sh_flag = (v >= 1.0f) ? 1.0f : 0.0f;
        }
        __syncthreads();
        if (sh_flag > 0.5f) lo = mid; else hi = mid;
    }

    float tau = 0.5f * (lo + hi);
    float s = 0.0f;
    #pragma unroll
    for (int k = 0; k < 32; k++) s += fmaxf(z[k] - tau, 0.0f);
    #pragma unroll
    for (int o = 16; o > 0; o >>= 1) s += __shfl_xor_sync(0xffffffffu, s, o);
    __syncthreads();
    if (l == 0) red[w] = s;
    __syncthreads();
    if (t == 0) {
        float v = 0.0f;
        for (int i = 0; i < 16; i++) v += red[i];
        g_asum[b] = v;
    }

    #pragma unroll
    for (int k = 0; k < 32; k++) {
        float d = z[k] - tau;
        if (d > 0.0f) {
            int pos = atomicAdd(&sh_cnt, 1);
            g_supp[b * NITEMS + pos] = t + k * 512;
            g_swgt[b * NITEMS + pos] = d;
        }
    }
    __syncthreads();
    if (t == 0) g_cnt[b] = sh_cnt;
}

// ---------------- pass 2: list-driven weighted g-sum over the support ----------------
__global__ void __launch_bounds__(256) pass2_kernel(const float* __restrict__ x_items,
                                                    const float* __restrict__ wx1,
                                                    const float* __restrict__ bx1) {
    int b    = blockIdx.y;
    int t    = threadIdx.x;
    int slot = t >> 7;
    int j    = t & 127;

    int cnt = g_cnt[b];
    int first = blockIdx.x * 2;
    if (first >= cnt) return;

    __shared__ float ws[IDIM * D];
    __shared__ float bsx[D];
    __shared__ float xsh[2][IDIM];
    for (int k = t; k < IDIM * D; k += 256) ws[k] = wx1[k];
    if (t < D) bsx[t] = bx1[t];

    float acc = 0.0f;
    for (int idx0 = first; idx0 < cnt; idx0 += 16) {
        int idx = idx0 + slot;
        int valid = (idx < cnt);
        int n = valid ? g_supp[b * NITEMS + idx] : 0;
        float wgt = valid ? g_swgt[b * NITEMS + idx] : 0.0f;

        __syncthreads();
        if (j < IDIM) {
            xsh[slot][j] = valid ? x_items[((size_t)b * NITEMS + (size_t)n) * IDIM + j] : 0.0f;
        }
        __syncthreads();

        float a = bsx[j];
        #pragma unroll
        for (int i = 0; i < IDIM; i++) a = fmaf(xsh[slot][i], ws[i * D + j], a);
        acc = fmaf(wgt, gelu_f(a), acc);
    }
    atomicAdd(&g_sacc[b * D + j], acc);
}

// ---------------- finalize: z -> output MLP ----------------
__global__ void finalize_kernel(float* __restrict__ out,
                                const float* __restrict__ wx2, const float* __restrict__ bx2,
                                const float* __restrict__ wvp, const float* __restrict__ bvp,
                                const float* __restrict__ wp1, const float* __restrict__ bp1,
                                const float* __restrict__ wp2, const float* __restrict__ bp2) {
    int b = blockIdx.x;
    int j = threadIdx.x;
    __shared__ float sn[D], hb[D], zz[D], pp[D];

    sn[j] = g_sacc[b * D + j] / g_asum[b];
    __syncthreads();

    float acc = bx2[j];
    #pragma unroll 8
    for (int i = 0; i < D; i++) acc = fmaf(sn[i], wx2[i * D + j], acc);
    hb[j] = acc;
    __syncthreads();

    acc = bvp[j];
    #pragma unroll 8
    for (int i = 0; i < D; i++) acc = fmaf(hb[i], wvp[i * D + j], acc);
    zz[j] = acc;
    __syncthreads();

    acc = bp1[j];
    #pragma unroll 8
    for (int i = 0; i < D; i++) acc = fmaf(zz[i], wp1[i * D + j], acc);
    pp[j] = gelu_f(acc);
    __syncthreads();

    if (j < 10) {
        acc = bp2[j];
        #pragma unroll 8
        for (int i = 0; i < D; i++) acc = fmaf(pp[i], wp2[i * 10 + j], acc);
        out[b * 10 + j] = acc;
    }
}

// ---------------- launch ----------------
extern "C" void kernel_launch(void* const* d_in, const int* in_sizes, int n_in,
                              void* d_out, int out_size) {
    const float* x_items = (const float*)d_in[0];
    const float* x_query = (const float*)d_in[1];
    const float* wx1 = (const float*)d_in[2];  const float* bx1 = (const float*)d_in[3];
    const float* wx2 = (const float*)d_in[4];  const float* bx2 = (const float*)d_in[5];
    const float* wq1 = (const float*)d_in[6];  const float* bq1 = (const float*)d_in[7];
    const float* wq2 = (const float*)d_in[8];  const float* bq2 = (const float*)d_in[9];
    const float* wqp = (const float*)d_in[10]; const float* bqp = (const float*)d_in[11];
    const float* wkp = (const float*)d_in[12]; const float* bkp = (const float*)d_in[13];
    const float* wvp = (const float*)d_in[14]; const float* bvp = (const float*)d_in[15];
    const float* wp1 = (const float*)d_in[16]; const float* bp1 = (const float*)d_in[17];
    const float* wp2 = (const float*)d_in[18]; const float* bp2 = (const float*)d_in[19];
    float* out = (float*)d_out;

    prep_w_kernel<<<16, 256>>>(wx1);
    prep_kernel<<<B, D>>>(x_query, wq1, bq1, wq2, bq2, wqp, bqp, wkp, bkp, wx2, bx2);
    dim3 grid1(NITEMS / 128, B);
    pass1_mma_kernel<<<grid1, 256>>>(x_items, bx1);
    bisect_kernel<<<B, 512>>>();
    dim3 grid2(8, B);
    pass2_kernel<<<grid2, 256>>>(x_items, wx1, bx1);
    finalize_kernel<<<B, D>>>(out, wx2, bx2, wvp, bvp, wp1, bp1, wp2, bp2);
}

// round 16
// speedup vs baseline: 4.1058x; 1.0928x over previous
#include <cuda_runtime.h>
#include <cuda_bf16.h>
#include <cstdint>
#include <math.h>

#define B      32
#define NITEMS 16384
#define D      128
#define IDIM   64

// ---------------- device scratch (no allocation allowed) ----------------
__device__ float g_scores[B * NITEMS];
__device__ float g_u[B * D];
__device__ float g_const[B];
__device__ float g_asum[B];
__device__ float g_sacc[B * D];
__device__ int   g_supp[B * NITEMS];
__device__ float g_swgt[B * NITEMS];
__device__ int   g_cnt[B];
// Pre-packed B fragments for mma.sync m16n8k16 (row.col):
// index = ((part*4 + kc)*16 + nt)*32 + lane ; part 0 = w_hi, part 1 = w_lo
__device__ uint2 g_wfrag[2 * 4 * 16 * 32];

// Branch-free erf-gelu: Abramowitz-Stegun 7.1.26, |abs err| <= 1.5e-7 on erf.
__device__ __forceinline__ float gelu_f(float x) {
    float ax = fabsf(x) * 0.7071067811865476f;
    float t  = __fdividef(1.0f, fmaf(0.3275911f, ax, 1.0f));
    float p  = t * fmaf(t, fmaf(t, fmaf(t, fmaf(t, 1.061405429f, -1.453152027f),
                                        1.421413741f), -0.284496736f), 0.254829592f);
    float e  = __expf(-ax * ax);
    float erf_ax = fmaf(-p, e, 1.0f);
    return 0.5f * x * (1.0f + copysignf(erf_ax, x));
}

__device__ __forceinline__ uint32_t pack_bf16x2(float lo_val, float hi_val) {
    __nv_bfloat16 a = __float2bfloat16(lo_val);
    __nv_bfloat16 b = __float2bfloat16(hi_val);
    return (uint32_t)__bfloat16_as_ushort(a) | ((uint32_t)__bfloat16_as_ushort(b) << 16);
}

__device__ __forceinline__ void mma_bf16(float* c, const uint32_t* a, uint32_t b0, uint32_t b1) {
    asm volatile(
        "mma.sync.aligned.m16n8k16.row.col.f32.bf16.bf16.f32 "
        "{%0,%1,%2,%3}, {%4,%5,%6,%7}, {%8,%9}, {%0,%1,%2,%3};"
        : "+f"(c[0]), "+f"(c[1]), "+f"(c[2]), "+f"(c[3])
        : "r"(a[0]), "r"(a[1]), "r"(a[2]), "r"(a[3]), "r"(b0), "r"(b1));
}

// ---------------- prep (merged): query path (blocks < B) + w-frag pack (blocks >= B) ----
__global__ void prep_kernel(const float* __restrict__ x_query,
                            const float* __restrict__ wq1, const float* __restrict__ bq1,
                            const float* __restrict__ wq2, const float* __restrict__ bq2,
                            const float* __restrict__ wqp, const float* __restrict__ bqp,
                            const float* __restrict__ wkp, const float* __restrict__ bkp,
                            const float* __restrict__ wx2, const float* __restrict__ bx2,
                            const float* __restrict__ wx1) {
    if (blockIdx.x >= B) {
        // ---- pack wx1 into per-lane mma B fragments (4096 uint2) ----
        // b0 = {B[k0, n], B[k0+1, n]}, b1 = {B[k0+8, n], B[k0+9, n]},
        // k0 = kc*16 + (lane%4)*2, n = nt*8 + lane/4; part 0 = w_hi, part 1 = w_lo.
        int idx  = (blockIdx.x - B) * 128 + threadIdx.x;   // 0..4095
        int lane = idx & 31;
        int nt   = (idx >> 5) & 15;
        int kc   = (idx >> 9) & 3;
        int part = idx >> 11;
        int n    = nt * 8 + (lane >> 2);
        int k0   = kc * 16 + (lane & 3) * 2;

        float w[4];
        int kk[4] = {k0, k0 + 1, k0 + 8, k0 + 9};
        #pragma unroll
        for (int i = 0; i < 4; i++) {
            float wv = wx1[kk[i] * D + n];
            __nv_bfloat16 hi = __float2bfloat16(wv);
            w[i] = part ? (wv - __bfloat162float(hi)) : wv;
        }
        uint2 fr;
        fr.x = pack_bf16x2(w[0], w[1]);
        fr.y = pack_bf16x2(w[2], w[3]);
        g_wfrag[idx] = fr;
        return;
    }

    int b = blockIdx.x;
    int j = threadIdx.x;
    __shared__ float h1[D], hq[D], qv[D], av[D], red[D];

    g_sacc[b * D + j] = 0.0f;

    float xq = x_query[b];
    h1[j] = gelu_f(fmaf(xq, wq1[j], bq1[j]));
    __syncthreads();

    float acc = bq2[j];
    #pragma unroll 16
    for (int i = 0; i < D; i++) acc = fmaf(h1[i], wq2[i * D + j], acc);
    hq[j] = acc;
    __syncthreads();

    acc = bqp[j];
    #pragma unroll 16
    for (int i = 0; i < D; i++) acc = fmaf(hq[i], wqp[i * D + j], acc);
    qv[j] = acc;
    __syncthreads();

    acc = 0.0f;
    #pragma unroll 16
    for (int i = 0; i < D; i++) acc = fmaf(wkp[j * D + i], qv[i], acc);
    av[j] = acc;
    __syncthreads();

    float u = 0.0f;
    #pragma unroll 16
    for (int i = 0; i < D; i++) u = fmaf(wx2[j * D + i], av[i], u);

    const float scale = 0.08838834764831845f;
    g_u[b * D + j] = u * scale;

    red[j] = bx2[j] * av[j] + qv[j] * bkp[j];
    __syncthreads();
    for (int s = 64; s > 0; s >>= 1) {
        if (j < s) red[j] += red[j + s];
        __syncthreads();
    }
    if (j == 0) g_const[b] = red[0] * scale;
}

// ---------------- pass 1: mma.sync bf16x3 GEMM + gelu/dot epilogue ----------------
// Block: 8 warps x 16 items = 128 items. Per warp: 3 passes x 4 kchunks x 16 ntiles HMMA.
#define XS_STRIDE 68
__global__ void __launch_bounds__(256) pass1_mma_kernel(const float* __restrict__ x_items,
                                                        const float* __restrict__ bx1) {
    __shared__ float xs[128 * XS_STRIDE];
    __shared__ float bs[D], us[D];

    int t = threadIdx.x, warp = t >> 5, lane = t & 31;
    int b = blockIdx.y;
    int itemBase = blockIdx.x * 128;

    if (t < D) { bs[t] = bx1[t]; us[t] = g_u[b * D + t]; }

    // stage x tile [128 items][64] into padded smem (2 threads per row)
    {
        int row = t >> 1, half = t & 1;
        const float4* src = (const float4*)(x_items +
            ((size_t)b * NITEMS + (size_t)(itemBase + row)) * IDIM) + half * 8;
        float* dst = &xs[row * XS_STRIDE + half * 32];
        #pragma unroll
        for (int i = 0; i < 8; i++) *(float4*)(dst + i * 4) = src[i];
    }
    __syncthreads();

    // build A fragments (hi and lo) for 4 kchunks
    int r = warp * 16 + (lane >> 2);
    int kbase = (lane & 3) * 2;
    uint32_t ahi[4][4], alo[4][4];
    #pragma unroll
    for (int kc = 0; kc < 4; kc++) {
        int k0 = kc * 16 + kbase;
        float2 v00 = *(float2*)&xs[r * XS_STRIDE + k0];
        float2 v10 = *(float2*)&xs[(r + 8) * XS_STRIDE + k0];
        float2 v01 = *(float2*)&xs[r * XS_STRIDE + k0 + 8];
        float2 v11 = *(float2*)&xs[(r + 8) * XS_STRIDE + k0 + 8];
        float2 vv[4] = {v00, v10, v01, v11};
        #pragma unroll
        for (int i = 0; i < 4; i++) {
            __nv_bfloat16 hx = __float2bfloat16(vv[i].x);
            __nv_bfloat16 hy = __float2bfloat16(vv[i].y);
            ahi[kc][i] = (uint32_t)__bfloat16_as_ushort(hx) | ((uint32_t)__bfloat16_as_ushort(hy) << 16);
            alo[kc][i] = pack_bf16x2(vv[i].x - __bfloat162float(hx), vv[i].y - __bfloat162float(hy));
        }
    }

    float acc[16][4];
    #pragma unroll
    for (int nt = 0; nt < 16; nt++)
        #pragma unroll
        for (int i = 0; i < 4; i++) acc[nt][i] = 0.0f;

    // pass 0: x_hi * w_hi ; pass 1: x_lo * w_hi ; pass 2: x_hi * w_lo
    #pragma unroll
    for (int pass = 0; pass < 3; pass++) {
        int part = (pass == 2) ? 1 : 0;
        #pragma unroll
        for (int kc = 0; kc < 4; kc++) {
            const uint32_t* A = (pass == 1) ? alo[kc] : ahi[kc];
            const uint2* wf = &g_wfrag[((part * 4 + kc) * 16) * 32 + lane];
            #pragma unroll
            for (int nt = 0; nt < 16; nt++) {
                uint2 fr = wf[nt * 32];
                mma_bf16(acc[nt], A, fr.x, fr.y);
            }
        }
    }

    // epilogue: j = nt*8 + kbase + {0,1}; rows r (c0,c1) and r+8 (c2,c3)
    float s0 = 0.0f, s1 = 0.0f;
    #pragma unroll
    for (int nt = 0; nt < 16; nt++) {
        int j0 = nt * 8 + kbase;
        float u0 = us[j0], u1 = us[j0 + 1], b0 = bs[j0], b1 = bs[j0 + 1];
        s0 = fmaf(gelu_f(acc[nt][0] + b0), u0, s0);
        s0 = fmaf(gelu_f(acc[nt][1] + b1), u1, s0);
        s1 = fmaf(gelu_f(acc[nt][2] + b0), u0, s1);
        s1 = fmaf(gelu_f(acc[nt][3] + b1), u1, s1);
    }
    s0 += __shfl_xor_sync(0xffffffffu, s0, 1);
    s0 += __shfl_xor_sync(0xffffffffu, s0, 2);
    s1 += __shfl_xor_sync(0xffffffffu, s1, 1);
    s1 += __shfl_xor_sync(0xffffffffu, s1, 2);

    if ((lane & 3) == 0) {
        float cb = g_const[b];
        g_scores[b * NITEMS + itemBase + r]     = s0 + cb;
        g_scores[b * NITEMS + itemBase + r + 8] = s1 + cb;
    }
}

// ---------------- bisection for sparsemax tau + support compaction ----------------
__global__ void __launch_bounds__(512) bisect_kernel() {
    int b = blockIdx.x;
    int t = threadIdx.x;
    int w = t >> 5, l = t & 31;

    const float4* sp = (const float4*)(g_scores + b * NITEMS);
    float z[32];
    #pragma unroll
    for (int k = 0; k < 8; k++) {
        float4 v = sp[t * 8 + k];                 // items [t*32, t*32+32)
        z[4 * k + 0] = v.x; z[4 * k + 1] = v.y;
        z[4 * k + 2] = v.z; z[4 * k + 3] = v.w;
    }

    float m = z[0];
    #pragma unroll
    for (int k = 1; k < 32; k++) m = fmaxf(m, z[k]);
    __shared__ float red[16];
    __shared__ float sh_flag;
    __shared__ int   sh_cnt;
    #pragma unroll
    for (int o = 16; o > 0; o >>= 1) m = fmaxf(m, __shfl_xor_sync(0xffffffffu, m, o));
    if (l == 0) red[w] = m;
    __syncthreads();
    if (t == 0) {
        float v = red[0];
        for (int i = 1; i < 16; i++) v = fmaxf(v, red[i]);
        red[0] = v;
        sh_cnt = 0;
    }
    __syncthreads();
    float zmax = red[0];
    __syncthreads();

    float lo = zmax - 1.0f, hi = zmax;
    for (int it = 0; it < 28; it++) {
        float mid = 0.5f * (lo + hi);
        float s = 0.0f;
        #pragma unroll
        for (int k = 0; k < 32; k++) s += fmaxf(z[k] - mid, 0.0f);
        #pragma unroll
        for (int o = 16; o > 0; o >>= 1) s += __shfl_xor_sync(0xffffffffu, s, o);
        __syncthreads();
        if (l == 0) red[w] = s;
        __syncthreads();
        if (t == 0) {
            float v = 0.0f;
            for (int i = 0; i < 16; i++) v += red[i];
            sh_flag = (v >= 1.0f) ? 1.0f : 0.0f;
        }
        __syncthreads();
        if (sh_flag > 0.5f) lo = mid; else hi = mid;
    }

    float tau = 0.5f * (lo + hi);
    float s = 0.0f;
    #pragma unroll
    for (int k = 0; k < 32; k++) s += fmaxf(z[k] - tau, 0.0f);
    #pragma unroll
    for (int o = 16; o > 0; o >>= 1) s += __shfl_xor_sync(0xffffffffu, s, o);
    __syncthreads();
    if (l == 0) red[w] = s;
    __syncthreads();
    if (t == 0) {
        float v = 0.0f;
        for (int i = 0; i < 16; i++) v += red[i];
        g_asum[b] = v;
    }

    #pragma unroll
    for (int k = 0; k < 32; k++) {
        float d = z[k] - tau;
        if (d > 0.0f) {
            int pos = atomicAdd(&sh_cnt, 1);
            g_supp[b * NITEMS + pos] = t * 32 + k;
            g_swgt[b * NITEMS + pos] = d;
        }
    }
    __syncthreads();
    if (t == 0) g_cnt[b] = sh_cnt;
}

// ---------------- pass 2: list-driven weighted g-sum over the support ----------------
// grid (32, B), 256 threads = 2 item-slots x 128 j-lanes.
__global__ void __launch_bounds__(256) pass2_kernel(const float* __restrict__ x_items,
                                                    const float* __restrict__ wx1,
                                                    const float* __restrict__ bx1) {
    int b    = blockIdx.y;
    int t    = threadIdx.x;
    int slot = t >> 7;
    int j    = t & 127;

    int cnt = g_cnt[b];
    int first = blockIdx.x * 2;
    if (first >= cnt) return;
    int stride = gridDim.x * 2;

    __shared__ float ws[IDIM * D];
    __shared__ float bsx[D];
    __shared__ float xsh[2][IDIM];
    for (int k = t; k < IDIM * D; k += 256) ws[k] = wx1[k];
    if (t < D) bsx[t] = bx1[t];

    float acc = 0.0f;
    for (int idx0 = first; idx0 < cnt; idx0 += stride) {
        int idx = idx0 + slot;
        int valid = (idx < cnt);
        int n = valid ? g_supp[b * NITEMS + idx] : 0;
        float wgt = valid ? g_swgt[b * NITEMS + idx] : 0.0f;

        __syncthreads();
        if (j < IDIM) {
            xsh[slot][j] = valid ? x_items[((size_t)b * NITEMS + (size_t)n) * IDIM + j] : 0.0f;
        }
        __syncthreads();

        float a = bsx[j];
        #pragma unroll
        for (int i = 0; i < IDIM; i++) a = fmaf(xsh[slot][i], ws[i * D + j], a);
        acc = fmaf(wgt, gelu_f(a), acc);
    }
    atomicAdd(&g_sacc[b * D + j], acc);
}

// ---------------- finalize: z -> output MLP ----------------
__global__ void finalize_kernel(float* __restrict__ out,
                                const float* __restrict__ wx2, const float* __restrict__ bx2,
                                const float* __restrict__ wvp, const float* __restrict__ bvp,
                                const float* __restrict__ wp1, const float* __restrict__ bp1,
                                const float* __restrict__ wp2, const float* __restrict__ bp2) {
    int b = blockIdx.x;
    int j = threadIdx.x;
    __shared__ float sn[D], hb[D], zz[D], pp[D];

    sn[j] = g_sacc[b * D + j] / g_asum[b];
    __syncthreads();

    float acc = bx2[j];
    #pragma unroll 16
    for (int i = 0; i < D; i++) acc = fmaf(sn[i], wx2[i * D + j], acc);
    hb[j] = acc;
    __syncthreads();

    acc = bvp[j];
    #pragma unroll 16
    for (int i = 0; i < D; i++) acc = fmaf(hb[i], wvp[i * D + j], acc);
    zz[j] = acc;
    __syncthreads();

    acc = bp1[j];
    #pragma unroll 16
    for (int i = 0; i < D; i++) acc = fmaf(zz[i], wp1[i * D + j], acc);
    pp[j] = gelu_f(acc);
    __syncthreads();

    if (j < 10) {
        acc = bp2[j];
        #pragma unroll 16
        for (int i = 0; i < D; i++) acc = fmaf(pp[i], wp2[i * 10 + j], acc);
        out[b * 10 + j] = acc;
    }
}

// ---------------- launch ----------------
extern "C" void kernel_launch(void* const* d_in, const int* in_sizes, int n_in,
                              void* d_out, int out_size) {
    const float* x_items = (const float*)d_in[0];
    const float* x_query = (const float*)d_in[1];
    const float* wx1 = (const float*)d_in[2];  const float* bx1 = (const float*)d_in[3];
    const float* wx2 = (const float*)d_in[4];  const float* bx2 = (const float*)d_in[5];
    const float* wq1 = (const float*)d_in[6];  const float* bq1 = (const float*)d_in[7];
    const float* wq2 = (const float*)d_in[8];  const float* bq2 = (const float*)d_in[9];
    const float* wqp = (const float*)d_in[10]; const float* bqp = (const float*)d_in[11];
    const float* wkp = (const float*)d_in[12]; const float* bkp = (const float*)d_in[13];
    const float* wvp = (const float*)d_in[14]; const float* bvp = (const float*)d_in[15];
    const float* wp1 = (const float*)d_in[16]; const float* bp1 = (const float*)d_in[17];
    const float* wp2 = (const float*)d_in[18]; const float* bp2 = (const float*)d_in[19];
    float* out = (float*)d_out;

    prep_kernel<<<B + 32, D>>>(x_query, wq1, bq1, wq2, bq2, wqp, bqp, wkp, bkp, wx2, bx2, wx1);
    dim3 grid1(NITEMS / 128, B);
    pass1_mma_kernel<<<grid1, 256>>>(x_items, bx1);
    bisect_kernel<<<B, 512>>>();
    dim3 grid2(32, B);
    pass2_kernel<<<grid2, 256>>>(x_items, wx1, bx1);
    finalize_kernel<<<B, D>>>(out, wx2, bx2, wvp, bvp, wp1, bp1, wp2, bp2);
}